// round 11
// baseline (speedup 1.0000x reference)
#include <cuda_runtime.h>
#include <cuda_fp16.h>
#include <stdint.h>

// out[num_rows, 128] = segment_sum(W[cols]*vals, rows) + b
//
// R10: gather is latency-exposure bound at the per-row level.
//   k2 now processes 2 rows per warp: int2 counter load, both slot streams
//   preloaded unconditionally in parallel, interleaved inner loops
//   (FFMA2 path from R9), per-warp epilogue amortized over 2 rows.
//   g_cnt self-resets inside gather (plain store, no fence/done counter);
//   zero_kernel shrinks to a 1-warp g_ovf_n reset.

static constexpr int UNITS    = 128;
static constexpr int WCOLS    = 8192;
static constexpr int SLOTS    = 48;
static constexpr int MAX_ROWS = 1 << 17;
static constexpr int OVF_CAP  = 65536;

__device__ __align__(16) __half g_Wh[WCOLS * UNITS];  // 2 MB fp16 W
__device__ __align__(8) int g_cnt[MAX_ROWS];          // self-reset by gather
__device__ float2 g_slot[(size_t)MAX_ROWS * SLOTS];   // (val, bitcast(col))
__device__ float4 g_ovf[OVF_CAP];                     // (val, col, row, -)
__device__ int    g_ovf_n;

__device__ __forceinline__ unsigned long long h2_to_f32x2(uint32_t h2) {
    unsigned long long w;
    asm("{\n\t"
        ".reg .f16 h0, h1;\n\t"
        ".reg .f32 f0, f1;\n\t"
        "mov.b32 {h0, h1}, %1;\n\t"
        "cvt.f32.f16 f0, h0;\n\t"
        "cvt.f32.f16 f1, h1;\n\t"
        "mov.b64 %0, {f0, f1};\n\t"
        "}" : "=l"(w) : "r"(h2));
    return w;
}

__device__ __forceinline__ unsigned long long dup_f32x2(float v) {
    unsigned long long w;
    asm("mov.b64 %0, {%1, %1};" : "=l"(w) : "f"(v));
    return w;
}

__device__ __forceinline__ void ffma2(unsigned long long& acc,
                                      unsigned long long a,
                                      unsigned long long b) {
    asm("fma.rn.f32x2 %0, %1, %2, %0;" : "+l"(acc) : "l"(a), "l"(b));
}

__device__ __forceinline__ float2 unpack_f32x2(unsigned long long w) {
    float lo, hi;
    asm("mov.b64 {%0, %1}, %2;" : "=f"(lo), "=f"(hi) : "l"(w));
    return make_float2(lo, hi);
}

// ---- k0: reset overflow counter only (g_cnt self-resets in gather) ----
__global__ void zero_kernel() {
    if (threadIdx.x == 0) g_ovf_n = 0;
}

__device__ __forceinline__ void bin_one(float v, int r, int c) {
    int pos = atomicAdd(&g_cnt[r], 1);
    if (pos < SLOTS) {
        g_slot[(size_t)r * SLOTS + pos] = make_float2(v, __int_as_float(c));
    } else {
        int op = atomicAdd(&g_ovf_n, 1);
        if (op < OVF_CAP)
            g_ovf[op] = make_float4(v, __int_as_float(c), __int_as_float(r), 0.f);
    }
}

// ---- k1: scatter nonzeros into per-row slots (2/thread) + convert W ----
__global__ void scatter_convert_kernel(const float* __restrict__ vals,
                                       const int* __restrict__ rows,
                                       const int* __restrict__ cols,
                                       const float* __restrict__ W,
                                       int nnz, int n4) {
    int t = blockIdx.x * blockDim.x + threadIdx.x;

    if (t < n4) {
        float4 f = __ldg(reinterpret_cast<const float4*>(W) + t);
        __half2 h0 = __floats2half2_rn(f.x, f.y);
        __half2 h1 = __floats2half2_rn(f.z, f.w);
        uint2 u;
        u.x = *reinterpret_cast<uint32_t*>(&h0);
        u.y = *reinterpret_cast<uint32_t*>(&h1);
        reinterpret_cast<uint2*>(g_Wh)[t] = u;
    }

    int i0 = t * 2;
    if (i0 >= nnz) return;

    if (i0 + 2 <= nnz) {
        float2 v2 = __ldg(reinterpret_cast<const float2*>(vals + i0));
        int2   r2 = __ldg(reinterpret_cast<const int2*>(rows + i0));
        int2   c2 = __ldg(reinterpret_cast<const int2*>(cols + i0));
        int pos0 = atomicAdd(&g_cnt[r2.x], 1);
        int pos1 = atomicAdd(&g_cnt[r2.y], 1);
        if (pos0 < SLOTS) {
            g_slot[(size_t)r2.x * SLOTS + pos0] = make_float2(v2.x, __int_as_float(c2.x));
        } else {
            int op = atomicAdd(&g_ovf_n, 1);
            if (op < OVF_CAP)
                g_ovf[op] = make_float4(v2.x, __int_as_float(c2.x), __int_as_float(r2.x), 0.f);
        }
        if (pos1 < SLOTS) {
            g_slot[(size_t)r2.y * SLOTS + pos1] = make_float2(v2.y, __int_as_float(c2.y));
        } else {
            int op = atomicAdd(&g_ovf_n, 1);
            if (op < OVF_CAP)
                g_ovf[op] = make_float4(v2.y, __int_as_float(c2.y), __int_as_float(r2.y), 0.f);
        }
    } else {
        bin_one(vals[i0], rows[i0], cols[i0]);
    }
}

// ---- k2: warp per TWO rows; half-warp split; FFMA2 accumulators ----
__global__ void __launch_bounds__(256) row_gather_kernel(
        const float* __restrict__ b,
        float* __restrict__ out,
        int num_rows) {
    int warp = (blockIdx.x * blockDim.x + threadIdx.x) >> 5;
    int lane = threadIdx.x & 31;
    int r0 = warp * 2;
    if (r0 >= num_rows) return;
    bool has_r1 = (r0 + 1) < num_rows;

    int hi  = lane >> 4;
    int sub = lane & 15;

    // Parallel prologue: counters (one int2) + both slot streams, all
    // independent LDGs issued before any dependency resolves.
    int2 cp = *reinterpret_cast<const int2*>(&g_cnt[r0]);   // r0 even -> aligned
    const float2* slots0 = g_slot + (size_t)r0 * SLOTS;
    const float2* slots1 = slots0 + SLOTS;
    float2 p0 = __ldg(slots0 + lane);   // unconditional: lane < 48 in-bounds;
    float2 p1 = __ldg(slots1 + lane);   // garbage masked by selects below

    int cnt0 = cp.x > SLOTS ? SLOTS : cp.x;
    int cnt1 = has_r1 ? (cp.y > SLOTS ? SLOTS : cp.y) : 0;
    int ovn = g_ovf_n;

    const char* Wl = reinterpret_cast<const char*>(g_Wh) + sub * 16;

    // Chunk 1 (covers cnt <= 32; ~99.6% of rows need nothing more).
    int m0 = cnt0 > 32 ? 32 : cnt0;
    int m1 = cnt1 > 32 ? 32 : cnt1;
    float v0 = (lane < m0) ? p0.x : 0.f;
    int   c0 = (lane < m0) ? __float_as_int(p0.y) : 0;
    float v1 = (lane < m1) ? p1.x : 0.f;
    int   c1 = (lane < m1) ? __float_as_int(p1.y) : 0;

    unsigned long long a00 = 0, a01 = 0, a02 = 0, a03 = 0;  // row0
    unsigned long long a10 = 0, a11 = 0, a12 = 0, a13 = 0;  // row1

    int it0 = (m0 + 1) >> 1;
    int it1 = (m1 + 1) >> 1;
    int itmax = it0 > it1 ? it0 : it1;
    #pragma unroll 4
    for (int p = 0; p < itmax; ++p) {
        int j = 2 * p + hi;
        if (p < it0) {
            float vj = __shfl_sync(0xffffffffu, v0, j);
            int   cj = __shfl_sync(0xffffffffu, c0, j);
            uint4 u = __ldg(reinterpret_cast<const uint4*>(
                          Wl + ((size_t)(uint32_t)cj << 8)));
            unsigned long long vv = dup_f32x2(vj);
            ffma2(a00, h2_to_f32x2(u.x), vv);
            ffma2(a01, h2_to_f32x2(u.y), vv);
            ffma2(a02, h2_to_f32x2(u.z), vv);
            ffma2(a03, h2_to_f32x2(u.w), vv);
        }
        if (p < it1) {
            float vj = __shfl_sync(0xffffffffu, v1, j);
            int   cj = __shfl_sync(0xffffffffu, c1, j);
            uint4 u = __ldg(reinterpret_cast<const uint4*>(
                          Wl + ((size_t)(uint32_t)cj << 8)));
            unsigned long long vv = dup_f32x2(vj);
            ffma2(a10, h2_to_f32x2(u.x), vv);
            ffma2(a11, h2_to_f32x2(u.y), vv);
            ffma2(a12, h2_to_f32x2(u.z), vv);
            ffma2(a13, h2_to_f32x2(u.w), vv);
        }
    }

    // Rare second chunk (cnt > 32), per row, conditional loads.
    if (cnt0 > 32) {
        int m = cnt0 - 32;
        float v = 0.f; int c = 0;
        if (lane < m) {
            float2 p = __ldg(slots0 + 32 + lane);
            v = p.x; c = __float_as_int(p.y);
        }
        int iters = (m + 1) >> 1;
        for (int p = 0; p < iters; ++p) {
            int j = 2 * p + hi;
            float vj = __shfl_sync(0xffffffffu, v, j);
            int   cj = __shfl_sync(0xffffffffu, c, j);
            uint4 u = __ldg(reinterpret_cast<const uint4*>(
                          Wl + ((size_t)(uint32_t)cj << 8)));
            unsigned long long vv = dup_f32x2(vj);
            ffma2(a00, h2_to_f32x2(u.x), vv);
            ffma2(a01, h2_to_f32x2(u.y), vv);
            ffma2(a02, h2_to_f32x2(u.z), vv);
            ffma2(a03, h2_to_f32x2(u.w), vv);
        }
    }
    if (cnt1 > 32) {
        int m = cnt1 - 32;
        float v = 0.f; int c = 0;
        if (lane < m) {
            float2 p = __ldg(slots1 + 32 + lane);
            v = p.x; c = __float_as_int(p.y);
        }
        int iters = (m + 1) >> 1;
        for (int p = 0; p < iters; ++p) {
            int j = 2 * p + hi;
            float vj = __shfl_sync(0xffffffffu, v, j);
            int   cj = __shfl_sync(0xffffffffu, c, j);
            uint4 u = __ldg(reinterpret_cast<const uint4*>(
                          Wl + ((size_t)(uint32_t)cj << 8)));
            unsigned long long vv = dup_f32x2(vj);
            ffma2(a10, h2_to_f32x2(u.x), vv);
            ffma2(a11, h2_to_f32x2(u.y), vv);
            ffma2(a12, h2_to_f32x2(u.z), vv);
            ffma2(a13, h2_to_f32x2(u.w), vv);
        }
    }

    // Epilogue: unpack, combine halves, bias (loaded once), two stores.
    int ubase = sub * 8 + hi * 4;
    float4 bias = __ldg(reinterpret_cast<const float4*>(b) + (ubase >> 2));

    float2 q0 = unpack_f32x2(a00), q1 = unpack_f32x2(a01);
    float2 q2 = unpack_f32x2(a02), q3 = unpack_f32x2(a03);
    float4 A = make_float4(q0.x, q0.y, q1.x, q1.y);
    float4 B = make_float4(q2.x, q2.y, q3.x, q3.y);
    A.x += __shfl_xor_sync(0xffffffffu, A.x, 16);
    A.y += __shfl_xor_sync(0xffffffffu, A.y, 16);
    A.z += __shfl_xor_sync(0xffffffffu, A.z, 16);
    A.w += __shfl_xor_sync(0xffffffffu, A.w, 16);
    B.x += __shfl_xor_sync(0xffffffffu, B.x, 16);
    B.y += __shfl_xor_sync(0xffffffffu, B.y, 16);
    B.z += __shfl_xor_sync(0xffffffffu, B.z, 16);
    B.w += __shfl_xor_sync(0xffffffffu, B.w, 16);
    float4 r0out = hi ? B : A;

    q0 = unpack_f32x2(a10); q1 = unpack_f32x2(a11);
    q2 = unpack_f32x2(a12); q3 = unpack_f32x2(a13);
    A = make_float4(q0.x, q0.y, q1.x, q1.y);
    B = make_float4(q2.x, q2.y, q3.x, q3.y);
    A.x += __shfl_xor_sync(0xffffffffu, A.x, 16);
    A.y += __shfl_xor_sync(0xffffffffu, A.y, 16);
    A.z += __shfl_xor_sync(0xffffffffu, A.z, 16);
    A.w += __shfl_xor_sync(0xffffffffu, A.w, 16);
    B.x += __shfl_xor_sync(0xffffffffu, B.x, 16);
    B.y += __shfl_xor_sync(0xffffffffu, B.y, 16);
    B.z += __shfl_xor_sync(0xffffffffu, B.z, 16);
    B.w += __shfl_xor_sync(0xffffffffu, B.w, 16);
    float4 r1out = hi ? B : A;

    // Inline overflow fixup (expected empty), both rows in one pass.
    if (ovn > 0) {
        if (ovn > OVF_CAP) ovn = OVF_CAP;
        for (int e = 0; e < ovn; ++e) {
            float4 ent = g_ovf[e];
            int er = __float_as_int(ent.z);
            if (er == r0 || (has_r1 && er == r0 + 1)) {
                float ve = ent.x;
                size_t ce = (size_t)(uint32_t)__float_as_int(ent.y);
                uint2 u = __ldg(reinterpret_cast<const uint2*>(
                              g_Wh + ce * UNITS + ubase));
                float2 e0 = __half22float2(*reinterpret_cast<__half2*>(&u.x));
                float2 e1 = __half22float2(*reinterpret_cast<__half2*>(&u.y));
                float4& tgt = (er == r0) ? r0out : r1out;
                tgt.x = fmaf(e0.x, ve, tgt.x);
                tgt.y = fmaf(e0.y, ve, tgt.y);
                tgt.z = fmaf(e1.x, ve, tgt.z);
                tgt.w = fmaf(e1.y, ve, tgt.w);
            }
        }
    }

    r0out.x += bias.x; r0out.y += bias.y; r0out.z += bias.z; r0out.w += bias.w;
    *reinterpret_cast<float4*>(out + (size_t)r0 * UNITS + ubase) = r0out;
    if (has_r1) {
        r1out.x += bias.x; r1out.y += bias.y; r1out.z += bias.z; r1out.w += bias.w;
        *reinterpret_cast<float4*>(out + (size_t)(r0 + 1) * UNITS + ubase) = r1out;
    }

    // Self-reset both counters (only this warp reads them; next scatter
    // runs after this kernel completes in stream order -> no fence needed).
    if (lane == 0)
        *reinterpret_cast<int2*>(&g_cnt[r0]) = make_int2(0, 0);
}

extern "C" void kernel_launch(void* const* d_in, const int* in_sizes, int n_in,
                              void* d_out, int out_size) {
    const float* vals = (const float*)d_in[0];
    const int*   rows = (const int*)d_in[1];
    const int*   cols = (const int*)d_in[2];
    const float* W    = (const float*)d_in[3];
    const float* b    = (const float*)d_in[4];
    float* out = (float*)d_out;

    int nnz = in_sizes[0];
    int num_rows = out_size / UNITS;

    const int T = 256;
    int n4 = WCOLS * UNITS / 4;
    int nh = (nnz + 1) / 2;
    int work = nh > n4 ? nh : n4;

    zero_kernel<<<1, 32>>>();
    scatter_convert_kernel<<<(work + T - 1) / T, T>>>(vals, rows, cols, W, nnz, n4);
    int nwarps = (num_rows + 1) / 2;
    int gblocks = (int)(((long)nwarps * 32 + T - 1) / T);
    row_gather_kernel<<<gblocks, T>>>(b, out, num_rows);
}

// round 12
// speedup vs baseline: 1.2485x; 1.2485x over previous
#include <cuda_runtime.h>
#include <cuda_fp16.h>
#include <stdint.h>

// out[num_rows, 128] = segment_sum(W[cols]*vals, rows) + b
//
// R11: base = R9 (86.53us best). Single change in row_gather: the first
// 32-slot metadata load issues unconditionally, in parallel with the
// per-row count load (always in-bounds: lane < 32 <= SLOTS). Removes one
// serialized L2 round-trip from every row's prologue. Everything else
// (scatter+convert, zero, FFMA2 inner loop) identical to R9.

static constexpr int UNITS    = 128;
static constexpr int WCOLS    = 8192;
static constexpr int SLOTS    = 48;
static constexpr int MAX_ROWS = 1 << 17;
static constexpr int OVF_CAP  = 65536;

__device__ __align__(16) __half g_Wh[WCOLS * UNITS];  // 2 MB fp16 W
__device__ int    g_cnt[MAX_ROWS];
__device__ float2 g_slot[(size_t)MAX_ROWS * SLOTS];   // (val, bitcast(col))
__device__ float4 g_ovf[OVF_CAP];                     // (val, col, row, -)
__device__ int    g_ovf_n;

__device__ __forceinline__ unsigned long long h2_to_f32x2(uint32_t h2) {
    unsigned long long w;
    asm("{\n\t"
        ".reg .f16 h0, h1;\n\t"
        ".reg .f32 f0, f1;\n\t"
        "mov.b32 {h0, h1}, %1;\n\t"
        "cvt.f32.f16 f0, h0;\n\t"
        "cvt.f32.f16 f1, h1;\n\t"
        "mov.b64 %0, {f0, f1};\n\t"
        "}" : "=l"(w) : "r"(h2));
    return w;
}

__device__ __forceinline__ unsigned long long dup_f32x2(float v) {
    unsigned long long w;
    asm("mov.b64 %0, {%1, %1};" : "=l"(w) : "f"(v));
    return w;
}

__device__ __forceinline__ void ffma2(unsigned long long& acc,
                                      unsigned long long a,
                                      unsigned long long b) {
    asm("fma.rn.f32x2 %0, %1, %2, %0;" : "+l"(acc) : "l"(a), "l"(b));
}

__device__ __forceinline__ float2 unpack_f32x2(unsigned long long w) {
    float lo, hi;
    asm("mov.b64 {%0, %1}, %2;" : "=f"(lo), "=f"(hi) : "l"(w));
    return make_float2(lo, hi);
}

// ---- k0: zero per-row counters + overflow counter ----
__global__ void zero_kernel(int num_rows) {
    int i = blockIdx.x * blockDim.x + threadIdx.x;
    if (i < num_rows) g_cnt[i] = 0;
    if (i == 0) g_ovf_n = 0;
}

__device__ __forceinline__ void bin_one(float v, int r, int c) {
    int pos = atomicAdd(&g_cnt[r], 1);
    if (pos < SLOTS) {
        g_slot[(size_t)r * SLOTS + pos] = make_float2(v, __int_as_float(c));
    } else {
        int op = atomicAdd(&g_ovf_n, 1);
        if (op < OVF_CAP)
            g_ovf[op] = make_float4(v, __int_as_float(c), __int_as_float(r), 0.f);
    }
}

// ---- k1: scatter nonzeros into per-row slots (2/thread) + convert W ----
__global__ void scatter_convert_kernel(const float* __restrict__ vals,
                                       const int* __restrict__ rows,
                                       const int* __restrict__ cols,
                                       const float* __restrict__ W,
                                       int nnz, int n4) {
    int t = blockIdx.x * blockDim.x + threadIdx.x;

    if (t < n4) {  // W conversion rides along on the first 262144 threads
        float4 f = __ldg(reinterpret_cast<const float4*>(W) + t);
        __half2 h0 = __floats2half2_rn(f.x, f.y);
        __half2 h1 = __floats2half2_rn(f.z, f.w);
        uint2 u;
        u.x = *reinterpret_cast<uint32_t*>(&h0);
        u.y = *reinterpret_cast<uint32_t*>(&h1);
        reinterpret_cast<uint2*>(g_Wh)[t] = u;
    }

    int i0 = t * 2;
    if (i0 >= nnz) return;

    if (i0 + 2 <= nnz) {
        float2 v2 = __ldg(reinterpret_cast<const float2*>(vals + i0));
        int2   r2 = __ldg(reinterpret_cast<const int2*>(rows + i0));
        int2   c2 = __ldg(reinterpret_cast<const int2*>(cols + i0));
        int pos0 = atomicAdd(&g_cnt[r2.x], 1);
        int pos1 = atomicAdd(&g_cnt[r2.y], 1);
        if (pos0 < SLOTS) {
            g_slot[(size_t)r2.x * SLOTS + pos0] = make_float2(v2.x, __int_as_float(c2.x));
        } else {
            int op = atomicAdd(&g_ovf_n, 1);
            if (op < OVF_CAP)
                g_ovf[op] = make_float4(v2.x, __int_as_float(c2.x), __int_as_float(r2.x), 0.f);
        }
        if (pos1 < SLOTS) {
            g_slot[(size_t)r2.y * SLOTS + pos1] = make_float2(v2.y, __int_as_float(c2.y));
        } else {
            int op = atomicAdd(&g_ovf_n, 1);
            if (op < OVF_CAP)
                g_ovf[op] = make_float4(v2.y, __int_as_float(c2.y), __int_as_float(r2.y), 0.f);
        }
    } else {
        bin_one(vals[i0], rows[i0], cols[i0]);
    }
}

// ---- k2: warp per row; half-warp split; FFMA2; parallel prologue ----
__global__ void __launch_bounds__(256) row_gather_kernel(
        const float* __restrict__ b,
        float* __restrict__ out,
        int num_rows) {
    int warp = (blockIdx.x * blockDim.x + threadIdx.x) >> 5;
    int lane = threadIdx.x & 31;
    if (warp >= num_rows) return;

    int hi  = lane >> 4;        // which nonzero of the pair this lane serves
    int sub = lane & 15;        // covers units [8*sub, 8*sub+8)

    const float2* slots = g_slot + (size_t)warp * SLOTS;

    // Parallel prologue: count + first slot chunk are independent loads,
    // both issued before either resolves (lane < 32 <= SLOTS: in-bounds).
    int cnt_raw = g_cnt[warp];
    float2 pre = __ldg(slots + lane);

    int cnt = cnt_raw > SLOTS ? SLOTS : cnt_raw;

    const char* Wl = reinterpret_cast<const char*>(g_Wh) + sub * 16;

    unsigned long long acc0 = 0, acc1 = 0, acc2 = 0, acc3 = 0;

    // Chunk 1 from the preloaded data (covers cnt <= 32: ~all rows).
    int m0 = cnt > 32 ? 32 : cnt;
    {
        float v = (lane < m0) ? pre.x : 0.f;
        int   c = (lane < m0) ? __float_as_int(pre.y) : 0;

        int iters = (m0 + 1) >> 1;
        #pragma unroll 8
        for (int p = 0; p < iters; ++p) {
            int j  = 2 * p + hi;
            float vj = __shfl_sync(0xffffffffu, v, j);    // 0 if j >= m0
            int   cj = __shfl_sync(0xffffffffu, c, j);

            uint4 u = __ldg(reinterpret_cast<const uint4*>(
                          Wl + ((size_t)(uint32_t)cj << 8)));
            unsigned long long vv = dup_f32x2(vj);
            ffma2(acc0, h2_to_f32x2(u.x), vv);
            ffma2(acc1, h2_to_f32x2(u.y), vv);
            ffma2(acc2, h2_to_f32x2(u.z), vv);
            ffma2(acc3, h2_to_f32x2(u.w), vv);
        }
    }

    // Rare chunk 2 (cnt > 32): conditional load as before.
    if (cnt > 32) {
        int m = cnt - 32;
        float v = 0.f;
        int   c = 0;
        if (lane < m) {
            float2 p = __ldg(slots + 32 + lane);
            v = p.x;
            c = __float_as_int(p.y);
        }
        int iters = (m + 1) >> 1;
        for (int p = 0; p < iters; ++p) {
            int j  = 2 * p + hi;
            float vj = __shfl_sync(0xffffffffu, v, j);
            int   cj = __shfl_sync(0xffffffffu, c, j);

            uint4 u = __ldg(reinterpret_cast<const uint4*>(
                          Wl + ((size_t)(uint32_t)cj << 8)));
            unsigned long long vv = dup_f32x2(vj);
            ffma2(acc0, h2_to_f32x2(u.x), vv);
            ffma2(acc1, h2_to_f32x2(u.y), vv);
            ffma2(acc2, h2_to_f32x2(u.z), vv);
            ffma2(acc3, h2_to_f32x2(u.w), vv);
        }
    }

    // Unpack to scalars, then combine even/odd half-warp partials.
    float2 p0 = unpack_f32x2(acc0);
    float2 p1 = unpack_f32x2(acc1);
    float2 p2 = unpack_f32x2(acc2);
    float2 p3 = unpack_f32x2(acc3);
    float4 accA = make_float4(p0.x, p0.y, p1.x, p1.y);  // units [8s, 8s+4)
    float4 accB = make_float4(p2.x, p2.y, p3.x, p3.y);  // units [8s+4, 8s+8)

    accA.x += __shfl_xor_sync(0xffffffffu, accA.x, 16);
    accA.y += __shfl_xor_sync(0xffffffffu, accA.y, 16);
    accA.z += __shfl_xor_sync(0xffffffffu, accA.z, 16);
    accA.w += __shfl_xor_sync(0xffffffffu, accA.w, 16);
    accB.x += __shfl_xor_sync(0xffffffffu, accB.x, 16);
    accB.y += __shfl_xor_sync(0xffffffffu, accB.y, 16);
    accB.z += __shfl_xor_sync(0xffffffffu, accB.z, 16);
    accB.w += __shfl_xor_sync(0xffffffffu, accB.w, 16);

    int ubase = sub * 8 + hi * 4;
    float4 r = hi ? accB : accA;

    // Inline overflow fixup (expected empty).
    int ovn = g_ovf_n;
    if (ovn > 0) {
        if (ovn > OVF_CAP) ovn = OVF_CAP;
        for (int e = 0; e < ovn; ++e) {
            float4 ent = g_ovf[e];
            if (__float_as_int(ent.z) == warp) {
                float ve = ent.x;
                size_t ce = (size_t)(uint32_t)__float_as_int(ent.y);
                uint2 u = __ldg(reinterpret_cast<const uint2*>(
                              g_Wh + ce * UNITS + ubase));
                float2 e0 = __half22float2(*reinterpret_cast<__half2*>(&u.x));
                float2 e1 = __half22float2(*reinterpret_cast<__half2*>(&u.y));
                r.x = fmaf(e0.x, ve, r.x);
                r.y = fmaf(e0.y, ve, r.y);
                r.z = fmaf(e1.x, ve, r.z);
                r.w = fmaf(e1.y, ve, r.w);
            }
        }
    }

    float4 bias = __ldg(reinterpret_cast<const float4*>(b) + (ubase >> 2));
    r.x += bias.x; r.y += bias.y; r.z += bias.z; r.w += bias.w;
    *reinterpret_cast<float4*>(out + (size_t)warp * UNITS + ubase) = r;
}

extern "C" void kernel_launch(void* const* d_in, const int* in_sizes, int n_in,
                              void* d_out, int out_size) {
    const float* vals = (const float*)d_in[0];
    const int*   rows = (const int*)d_in[1];
    const int*   cols = (const int*)d_in[2];
    const float* W    = (const float*)d_in[3];
    const float* b    = (const float*)d_in[4];
    float* out = (float*)d_out;

    int nnz = in_sizes[0];
    int num_rows = out_size / UNITS;

    const int T = 256;
    int n4 = WCOLS * UNITS / 4;             // 262144 float4s of W
    int nh = (nnz + 1) / 2;                 // threads for 2-wide scatter
    int work = nh > n4 ? nh : n4;

    zero_kernel<<<(num_rows + T - 1) / T, T>>>(num_rows);
    scatter_convert_kernel<<<(work + T - 1) / T, T>>>(vals, rows, cols, W, nnz, n4);
    int gblocks = (int)(((long)num_rows * 32 + T - 1) / T);
    row_gather_kernel<<<gblocks, T>>>(b, out, num_rows);
}